// round 1
// baseline (speedup 1.0000x reference)
#include <cuda_runtime.h>

// FlexMoERouter: logits[8192,16] = x*Wg + image*Wi + text*Wt + audio*Wa + (bg+bi+bt+ba)
// -> softmax -> top4 (renorm) -> aux loss.
// Output layout (float32): [0,32768) top_k_indices as float, [32768,65536) top_k_probs,
// [65536] aux_loss.

#define B_    4
#define S_    2048
#define H_    1024
#define E_    16
#define TOPK  4
#define NTOK  (B_ * S_)        // 8192
#define TPB   32               // tokens per block
#define NBLK  (NTOK / TPB)     // 256 blocks

__device__ float g_partial[NBLK][E_];   // per-block sum of router_probs per expert

// Accumulate one modality's contribution. Thread layout:
//   lane (0..31) = K-slice group, warp = (t_grp 0..3, e_grp 0..1)
//   thread owns acc[8 tokens][8 experts], partial over its K slice.
__device__ __forceinline__ void accum_input(
    const float* __restrict__ inp, const float* __restrict__ Wm,
    float acc[8][8], int tok0, int lane, int e0)
{
    const float4* xin = reinterpret_cast<const float4*>(inp);
#pragma unroll 1
    for (int c = 0; c < 8; c++) {          // 8 chunks of 128 k each
        float4 xv[8];
#pragma unroll
        for (int i = 0; i < 8; i++)
            xv[i] = xin[(size_t)(tok0 + i) * (H_ / 4) + c * 32 + lane];
        const int kbase = c * 128 + lane * 4;
#pragma unroll
        for (int kk = 0; kk < 4; kk++) {
            const float4* wr = reinterpret_cast<const float4*>(Wm + (size_t)(kbase + kk) * E_ + e0);
            float4 wA = wr[0];
            float4 wB = wr[1];
            float w[8] = {wA.x, wA.y, wA.z, wA.w, wB.x, wB.y, wB.z, wB.w};
#pragma unroll
            for (int i = 0; i < 8; i++) {
                float xs = (kk == 0) ? xv[i].x : (kk == 1) ? xv[i].y
                         : (kk == 2) ? xv[i].z : xv[i].w;
#pragma unroll
                for (int e = 0; e < 8; e++)
                    acc[i][e] = fmaf(xs, w[e], acc[i][e]);
            }
        }
    }
}

__global__ __launch_bounds__(256, 2)
void router_main(const float* __restrict__ x,   const float* __restrict__ img,
                 const float* __restrict__ txt, const float* __restrict__ aud,
                 const float* __restrict__ Wg,  const float* __restrict__ bg,
                 const float* __restrict__ Wi,  const float* __restrict__ bi,
                 const float* __restrict__ Wt,  const float* __restrict__ bt,
                 const float* __restrict__ Wa,  const float* __restrict__ ba,
                 float* __restrict__ out)
{
    const int tid   = threadIdx.x;
    const int lane  = tid & 31;
    const int warp  = tid >> 5;          // 0..7
    const int t_grp = warp & 3;          // token group
    const int e_grp = warp >> 2;         // expert group (0 or 1)
    const int tok0  = blockIdx.x * TPB + t_grp * 8;
    const int e0    = e_grp * 8;

    float acc[8][8];
#pragma unroll
    for (int i = 0; i < 8; i++)
#pragma unroll
        for (int e = 0; e < 8; e++) acc[i][e] = 0.0f;

    accum_input(x,   Wg, acc, tok0, lane, e0);
    accum_input(img, Wi, acc, tok0, lane, e0);
    accum_input(txt, Wt, acc, tok0, lane, e0);
    accum_input(aud, Wa, acc, tok0, lane, e0);

    // Reduce partial sums across the 32 lanes (K-slice dimension).
    __shared__ float sl[TPB][E_ + 1];    // +1 pad: conflict-free epilogue reads
#pragma unroll
    for (int i = 0; i < 8; i++) {
#pragma unroll
        for (int e = 0; e < 8; e++) {
            float v = acc[i][e];
            v += __shfl_xor_sync(0xffffffffu, v, 16);
            v += __shfl_xor_sync(0xffffffffu, v, 8);
            v += __shfl_xor_sync(0xffffffffu, v, 4);
            v += __shfl_xor_sync(0xffffffffu, v, 2);
            v += __shfl_xor_sync(0xffffffffu, v, 1);
            if (lane == 0) sl[t_grp * 8 + i][e0 + e] = v;
        }
    }
    __syncthreads();

    // Epilogue: warp 0, one thread per token.
    if (tid < TPB) {
        const int t = tid;
        const int g = blockIdx.x * TPB + t;

        float p[E_];
        float mx = -1e30f;
#pragma unroll
        for (int e = 0; e < E_; e++) {
            float l = sl[t][e] + bg[e] + bi[e] + bt[e] + ba[e];
            p[e] = l;
            mx = fmaxf(mx, l);
        }
        float s = 0.0f;
#pragma unroll
        for (int e = 0; e < E_; e++) { p[e] = expf(p[e] - mx); s += p[e]; }
        const float inv = 1.0f / s;
#pragma unroll
        for (int e = 0; e < E_; e++) p[e] *= inv;

        // Keep a copy of full probs for the expert-mean before top-k destroys p.
        float q[E_];
#pragma unroll
        for (int e = 0; e < E_; e++) q[e] = p[e];

        // top-4, descending, ties -> lowest index (matches jax.lax.top_k)
        float tp[TOPK];
        int   ti[TOPK];
        float tsum = 0.0f;
#pragma unroll
        for (int j = 0; j < TOPK; j++) {
            float best = -1.0f;
            int   bidx = 0;
#pragma unroll
            for (int e = 0; e < E_; e++) {
                if (p[e] > best) { best = p[e]; bidx = e; }
            }
            tp[j] = best;
            ti[j] = bidx;
            tsum += best;
            p[bidx] = -2.0f;
        }
        const float tinv = 1.0f / tsum;
#pragma unroll
        for (int j = 0; j < TOPK; j++) {
            out[(size_t)g * TOPK + j] = (float)ti[j];
            out[(size_t)NTOK * TOPK + (size_t)g * TOPK + j] = tp[j] * tinv;
        }

        // Per-expert prob sums across this block's 32 tokens (warp reduce, fixed order).
#pragma unroll
        for (int e = 0; e < E_; e++) {
            float v = q[e];
            v += __shfl_xor_sync(0xffffffffu, v, 16);
            v += __shfl_xor_sync(0xffffffffu, v, 8);
            v += __shfl_xor_sync(0xffffffffu, v, 4);
            v += __shfl_xor_sync(0xffffffffu, v, 2);
            v += __shfl_xor_sync(0xffffffffu, v, 1);
            if (tid == 0) g_partial[blockIdx.x][e] = v;
        }
    }
}

__global__ void router_finalize(float* __restrict__ out)
{
    __shared__ float sm[16][17];
    const int tid = threadIdx.x;        // 256 threads
    const int e   = tid & 15;
    const int grp = tid >> 4;           // 16 groups
    float v = 0.0f;
    for (int b = grp; b < NBLK; b += 16) v += g_partial[b][e];
    sm[grp][e] = v;
    __syncthreads();
    if (tid < 16) {
        float t = 0.0f;
#pragma unroll
        for (int g2 = 0; g2 < 16; g2++) t += sm[g2][tid];
        float pe = t / (float)NTOK;
        sm[0][tid] = pe * logf(pe * (float)E_ + 1e-9f);
    }
    __syncthreads();
    if (tid == 0) {
        float a = 0.0f;
#pragma unroll
        for (int e2 = 0; e2 < E_; e2++) a += sm[0][e2];
        out[(size_t)NTOK * TOPK * 2] = a;
    }
}

extern "C" void kernel_launch(void* const* d_in, const int* in_sizes, int n_in,
                              void* d_out, int out_size)
{
    (void)in_sizes; (void)n_in; (void)out_size;
    const float* x   = (const float*)d_in[0];
    const float* img = (const float*)d_in[1];
    const float* txt = (const float*)d_in[2];
    const float* aud = (const float*)d_in[3];
    const float* Wg  = (const float*)d_in[4];
    const float* bg  = (const float*)d_in[5];
    const float* Wi  = (const float*)d_in[6];
    const float* bi  = (const float*)d_in[7];
    const float* Wt  = (const float*)d_in[8];
    const float* bt  = (const float*)d_in[9];
    const float* Wa  = (const float*)d_in[10];
    const float* ba  = (const float*)d_in[11];
    float* out = (float*)d_out;

    router_main<<<NBLK, 256>>>(x, img, txt, aud, Wg, bg, Wi, bi, Wt, bt, Wa, ba, out);
    router_finalize<<<1, 256>>>(out);
}